// round 1
// baseline (speedup 1.0000x reference)
#include <cuda_runtime.h>
#include <cuda_bf16.h>

// Problem constants (fixed by the dataset)
constexpr int B = 8;
constexpr int L = 2048;
constexpr int D = 32;

constexpr int TI   = 256;                  // i/j tile size
constexpr int NT   = L / TI;               // 8 tiles per axis
constexpr int NTRI = NT * (NT + 1) / 2;    // 36 triangular tiles per batch

constexpr float LOG2E = 1.4426950408889634f;
// clip(exponent, -20, 0) in natural log -> clamp in log2 domain
constexpr float CLAMP2 = -20.0f * 1.4426950408889634f;   // -28.8539...

// Precomputed tables, transposed to [trigger][receiver] for conflict-free LDS:
//   g_tab[t*D + r] = { alpha[r][t]*beta[r][t],  -beta[r][t]*log2(e) }
__device__ float2 g_tab[D * D];

__device__ __forceinline__ float ex2f(float x) {
    float y;
    asm("ex2.approx.ftz.f32 %0, %1;" : "=f"(y) : "f"(x));
    return y;
}

__device__ __forceinline__ float softplusf(float x) {
    // accurate enough for rel_err 1e-3; inputs ~N(0,1)
    return log1pf(__expf(x));
}

__global__ void build_tab_kernel(const float* __restrict__ log_alpha,
                                 const float* __restrict__ log_beta) {
    int i = threadIdx.x;                 // i = r*D + t  (row-major [recv][trig])
    if (i < D * D) {
        int r = i >> 5;
        int t = i & (D - 1);
        float a  = softplusf(log_alpha[i]);
        float bt = softplusf(log_beta[i]);
        g_tab[t * D + r] = make_float2(a * bt, -bt * LOG2E);
    }
}

__global__ void zero_out_kernel(float* __restrict__ out) {
    int i = blockIdx.x * blockDim.x + threadIdx.x;
    if (i < B * L) out[i] = 0.0f;
}

__global__ __launch_bounds__(TI)
void hawkes_kernel(const float* __restrict__ time_points,
                   const int*   __restrict__ event_types,
                   float*       __restrict__ out) {
    __shared__ float2 s_tab[D * D];   // 8 KB
    __shared__ float2 s_j[TI];        // {t_j, float_bits(ct_j*32)}

    const int tid = threadIdx.x;
    const int blk = blockIdx.x;
    const int b   = blk / NTRI;
    const int k   = blk % NTRI;

    // triangular decode: k -> (ti, tj) with tj <= ti
    int ti = (int)((sqrtf(8.0f * (float)k + 1.0f) - 1.0f) * 0.5f);
    while ((ti + 1) * (ti + 2) / 2 <= k) ti++;
    while (ti * (ti + 1) / 2 > k) ti--;
    const int tj = k - ti * (ti + 1) / 2;

    // cooperative loads
    {
        const float4* src = reinterpret_cast<const float4*>(g_tab);
        float4*       dst = reinterpret_cast<float4*>(s_tab);
        // D*D float2 = 1024*8B = 512 float4
        dst[tid]       = src[tid];
        dst[tid + TI]  = src[tid + TI];
    }
    {
        const int jg = b * L + tj * TI + tid;
        float tjv = time_points[jg];
        int   ctj = event_types[jg];
        ctj = ctj < 0 ? 0 : ctj;
        s_j[tid] = make_float2(tjv, __int_as_float(ctj << 5));
    }
    __syncthreads();

    const int ig = b * L + ti * TI + tid;
    const float myt = time_points[ig];
    int r = event_types[ig];
    r = r < 0 ? 0 : r;

    float acc;
    if (ti != tj) {
        // strictly-lower tile: all j in tile satisfy j < i
        float a0 = 0.f, a1 = 0.f, a2 = 0.f, a3 = 0.f;
        #pragma unroll 1
        for (int j = 0; j < TI; j += 4) {
            {
                float2 p = s_j[j];
                float2 t2 = s_tab[__float_as_int(p.y) + r];
                float e = fmaxf(t2.y * (myt - p.x), CLAMP2);
                a0 = fmaf(t2.x, ex2f(e), a0);
            }
            {
                float2 p = s_j[j + 1];
                float2 t2 = s_tab[__float_as_int(p.y) + r];
                float e = fmaxf(t2.y * (myt - p.x), CLAMP2);
                a1 = fmaf(t2.x, ex2f(e), a1);
            }
            {
                float2 p = s_j[j + 2];
                float2 t2 = s_tab[__float_as_int(p.y) + r];
                float e = fmaxf(t2.y * (myt - p.x), CLAMP2);
                a2 = fmaf(t2.x, ex2f(e), a2);
            }
            {
                float2 p = s_j[j + 3];
                float2 t2 = s_tab[__float_as_int(p.y) + r];
                float e = fmaxf(t2.y * (myt - p.x), CLAMP2);
                a3 = fmaf(t2.x, ex2f(e), a3);
            }
        }
        acc = (a0 + a1) + (a2 + a3);
    } else {
        // diagonal tile: j (local) < tid enforces strict lower
        acc = 0.f;
        for (int j = 0; j < tid; ++j) {
            float2 p = s_j[j];
            float2 t2 = s_tab[__float_as_int(p.y) + r];
            float e = fmaxf(t2.y * (myt - p.x), CLAMP2);
            acc = fmaf(t2.x, ex2f(e), acc);
        }
    }

    atomicAdd(&out[ig], acc);
}

extern "C" void kernel_launch(void* const* d_in, const int* in_sizes, int n_in,
                              void* d_out, int out_size) {
    const float* time_points = (const float*)d_in[0];
    const int*   event_types = (const int*)d_in[1];
    const float* log_alpha   = (const float*)d_in[2];
    const float* log_beta    = (const float*)d_in[3];
    float* out = (float*)d_out;

    build_tab_kernel<<<1, D * D>>>(log_alpha, log_beta);
    zero_out_kernel<<<(B * L + 255) / 256, 256>>>(out);
    hawkes_kernel<<<B * NTRI, TI>>>(time_points, event_types, out);
}

// round 2
// speedup vs baseline: 1.1855x; 1.1855x over previous
#include <cuda_runtime.h>
#include <cuda_bf16.h>

// Hawkes pairwise interaction sum:
//   out[b,i] = sum_{j<i} a[r_i,t_j] * b[r_i,t_j] * exp(-b[r_i,t_j]*(T_i - T_j))
// B=8, L=2048, D=32. Times sorted ascending -> dt >= 0, exponent <= 0,
// so the reference's clip(-20,0) only flooring terms of magnitude <= 2e-9;
// we drop it (error ~1e-6 rel, threshold 1e-3).

constexpr int B = 8;
constexpr int L = 2048;
constexpr int D = 32;

constexpr int TI   = 256;                  // tile size
constexpr int NT   = L / TI;               // 8
constexpr int NTRI = NT * (NT + 1) / 2;    // 36 triangular tiles / batch

constexpr float LOG2E = 1.4426950408889634f;

__device__ __forceinline__ float ex2f(float x) {
    float y;
    asm("ex2.approx.ftz.f32 %0, %1;" : "=f"(y) : "f"(x));
    return y;
}

__device__ __forceinline__ float softplusf(float x) {
    // numerically stable softplus, only 8 evals/thread -> use precise funcs
    return fmaxf(x, 0.0f) + log1pf(expf(-fabsf(x)));
}

__global__ void zero_out_kernel(float* __restrict__ out) {
    int i = blockIdx.x * blockDim.x + threadIdx.x;
    if (i < B * L) out[i] = 0.0f;
}

__global__ __launch_bounds__(TI)
void hawkes_kernel(const float* __restrict__ time_points,
                   const int*   __restrict__ event_types,
                   const float* __restrict__ log_alpha,
                   const float* __restrict__ log_beta,
                   float*       __restrict__ out) {
    // Tables transposed to [trigger][receiver], split into two stride-32
    // float arrays so the per-pair gather (ctj uniform per warp-step, r per
    // lane) is bank-conflict-free.
    __shared__ float  s_ab[D * D];    // alpha*beta
    __shared__ float  s_nb[D * D];    // -beta*log2(e)
    __shared__ float2 s_j[TI];        // {t_j, int_bits(ct_j*32)}

    const int tid = threadIdx.x;
    const int blk = blockIdx.x;
    const int b   = blk / NTRI;
    const int k   = blk % NTRI;

    // Per-block table build (removes a serialized launch): 4 entries/thread.
    #pragma unroll
    for (int e = tid; e < D * D; e += TI) {
        int r = e >> 5;          // receiver
        int t = e & (D - 1);     // trigger
        float a  = softplusf(log_alpha[e]);
        float bt = softplusf(log_beta[e]);
        s_ab[t * D + r] = a * bt;
        s_nb[t * D + r] = -bt * LOG2E;
    }

    // triangular decode: k -> (ti_, tj_) with tj_ <= ti_
    int ti_ = (int)((sqrtf(8.0f * (float)k + 1.0f) - 1.0f) * 0.5f);
    while ((ti_ + 1) * (ti_ + 2) / 2 <= k) ti_++;
    while (ti_ * (ti_ + 1) / 2 > k) ti_--;
    const int tj_ = k - ti_ * (ti_ + 1) / 2;

    {
        const int jg = b * L + tj_ * TI + tid;
        float tjv = time_points[jg];
        int   ctj = event_types[jg];
        ctj = ctj < 0 ? 0 : ctj;
        s_j[tid] = make_float2(tjv, __int_as_float(ctj << 5));
    }
    __syncthreads();

    const int ig = b * L + ti_ * TI + tid;
    const float myt = time_points[ig];
    int r = event_types[ig];
    r = r < 0 ? 0 : r;

    float acc;
    if (ti_ != tj_) {
        // strictly-lower tile: every j in tile has j < i
        float a8[8];
        #pragma unroll
        for (int u = 0; u < 8; ++u) a8[u] = 0.0f;

        #pragma unroll 1
        for (int j = 0; j < TI; j += 8) {
            #pragma unroll
            for (int u = 0; u < 8; ++u) {
                float2 p  = s_j[j + u];
                int   idx = __float_as_int(p.y) + r;
                float e   = s_nb[idx] * (myt - p.x);
                a8[u] = fmaf(s_ab[idx], ex2f(e), a8[u]);
            }
        }
        acc = ((a8[0] + a8[1]) + (a8[2] + a8[3])) +
              ((a8[4] + a8[5]) + (a8[6] + a8[7]));
    } else {
        // diagonal tile: local j < tid enforces strict lower
        float a2[2] = {0.0f, 0.0f};
        int j = 0;
        for (; j + 2 <= tid; j += 2) {
            #pragma unroll
            for (int u = 0; u < 2; ++u) {
                float2 p  = s_j[j + u];
                int   idx = __float_as_int(p.y) + r;
                float e   = s_nb[idx] * (myt - p.x);
                a2[u] = fmaf(s_ab[idx], ex2f(e), a2[u]);
            }
        }
        if (j < tid) {
            float2 p  = s_j[j];
            int   idx = __float_as_int(p.y) + r;
            float e   = s_nb[idx] * (myt - p.x);
            a2[0] = fmaf(s_ab[idx], ex2f(e), a2[0]);
        }
        acc = a2[0] + a2[1];
    }

    atomicAdd(&out[ig], acc);
}

extern "C" void kernel_launch(void* const* d_in, const int* in_sizes, int n_in,
                              void* d_out, int out_size) {
    const float* time_points = (const float*)d_in[0];
    const int*   event_types = (const int*)d_in[1];
    const float* log_alpha   = (const float*)d_in[2];
    const float* log_beta    = (const float*)d_in[3];
    float* out = (float*)d_out;

    zero_out_kernel<<<(B * L + 255) / 256, 256>>>(out);
    hawkes_kernel<<<B * NTRI, TI>>>(time_points, event_types,
                                    log_alpha, log_beta, out);
}